// round 10
// baseline (speedup 1.0000x reference)
#include <cuda_runtime.h>

#define N_NODES 2000
#define BATCH 512
#define N_TOTAL (BATCH * N_NODES)      // 1,024,000
#define N_EDGES (16 * N_TOTAL)         // 16,384,000
#define SLOPE 0.01f
#define SLOTS 64                       // max degree; Poisson(16) tail @64 over 1M nodes ~ 1e-21
#define PLANES (SLOTS / 4)             // 16 planes of int4 (4 slots each)

// -------- device scratch (no allocation; BSS zero-init) --------
// Device globals are referenced ONLY from device code.
__device__ __align__(16) int  g_cursor[N_TOTAL];                    // degree after fill
__device__ __align__(16) int4 g_colT[(size_t)PLANES * N_TOTAL];     // transposed slot planes (hot: low planes)
__device__ __align__(16) float g_ya[(size_t)N_TOTAL * 8];
__device__ __align__(16) float g_yb[(size_t)N_TOTAL * 8];
__device__ __align__(16) float g_z[N_TOTAL];

__device__ __forceinline__ float leaky(float v) { return v > 0.0f ? v : SLOPE * v; }

// ---------------- pretransform + cursor zeroing ----------------
// g_ya = x @ w0a (bias folded by linearity); also zeroes g_cursor (fill runs after).
__global__ void k_pre(const float* __restrict__ x, const float* __restrict__ w0a) {
    __shared__ float sw[128];
    int t = threadIdx.x;
    if (t < 128) sw[t] = w0a[t];
    __syncthreads();
    unsigned i = blockIdx.x * blockDim.x + t;
    if (i >= (unsigned)N_TOTAL) return;

    g_cursor[i] = 0;   // coalesced; replaces the separate zero kernel

    float in[16];
    const float4* ax = reinterpret_cast<const float4*>(x + (size_t)i * 16);
#pragma unroll
    for (int q = 0; q < 4; q++) {
        float4 a = ax[q];
        in[4 * q] = a.x; in[4 * q + 1] = a.y; in[4 * q + 2] = a.z; in[4 * q + 3] = a.w;
    }
    float y[8];
#pragma unroll
    for (int j = 0; j < 8; j++) y[j] = 0.f;
#pragma unroll
    for (int k = 0; k < 16; k++) {
        float v = in[k];
#pragma unroll
        for (int j = 0; j < 8; j++) y[j] = fmaf(v, sw[k * 8 + j], y[j]);
    }
    float4* py = reinterpret_cast<float4*>(g_ya + (size_t)i * 8);
    py[0] = make_float4(y[0], y[1], y[2], y[3]);
    py[1] = make_float4(y[4], y[5], y[6], y[7]);
}

// ---------------- fill: 2 edges per thread, transposed slot store ----------------
__global__ void k_fill(const int* __restrict__ ei) {
    unsigned p = blockIdx.x * blockDim.x + threadIdx.x;   // edge-pair index
    if (p < (unsigned)(N_EDGES / 2)) {
        int2 src = __ldg(reinterpret_cast<const int2*>(ei) + p);
        int2 dst = __ldg(reinterpret_cast<const int2*>(ei + N_EDGES) + p);
        int pos0 = atomicAdd(&g_cursor[dst.x], 1);
        if (pos0 < SLOTS)
            reinterpret_cast<int*>(g_colT)[((size_t)(pos0 >> 2) * N_TOTAL + dst.x) * 4 + (pos0 & 3)] = src.x;
        int pos1 = atomicAdd(&g_cursor[dst.y], 1);
        if (pos1 < SLOTS)
            reinterpret_cast<int*>(g_colT)[((size_t)(pos1 >> 2) * N_TOTAL + dst.y) * 4 + (pos1 & 3)] = src.y;
    }
}

// ---------------- gather helper: 1 lane per node, full 8-wide accumulator ----------------
__device__ __forceinline__ void gather_node(const float* __restrict__ yin, unsigned node,
                                            float4& lo, float4& hi) {
    int deg = __ldg(&g_cursor[node]);
    if (deg > SLOTS) deg = SLOTS;

    const float4* yv = reinterpret_cast<const float4*>(yin);
    lo = __ldg(yv + (size_t)node * 2);        // self term
    hi = __ldg(yv + (size_t)node * 2 + 1);

    int nfull = deg >> 2;
    const int4* cpt = g_colT + node;          // stride N_TOTAL between planes
    for (int pl = 0; pl < nfull; pl++) {
        int4 c = __ldg(cpt + (size_t)pl * N_TOTAL);
        float4 a0 = __ldg(yv + (size_t)c.x * 2), b0 = __ldg(yv + (size_t)c.x * 2 + 1);
        float4 a1 = __ldg(yv + (size_t)c.y * 2), b1 = __ldg(yv + (size_t)c.y * 2 + 1);
        float4 a2 = __ldg(yv + (size_t)c.z * 2), b2 = __ldg(yv + (size_t)c.z * 2 + 1);
        float4 a3 = __ldg(yv + (size_t)c.w * 2), b3 = __ldg(yv + (size_t)c.w * 2 + 1);
        lo.x += a0.x + a1.x + a2.x + a3.x;  lo.y += a0.y + a1.y + a2.y + a3.y;
        lo.z += a0.z + a1.z + a2.z + a3.z;  lo.w += a0.w + a1.w + a2.w + a3.w;
        hi.x += b0.x + b1.x + b2.x + b3.x;  hi.y += b0.y + b1.y + b2.y + b3.y;
        hi.z += b0.z + b1.z + b2.z + b3.z;  hi.w += b0.w + b1.w + b2.w + b3.w;
    }
    int rem = deg & 3;
    if (rem) {
        int4 c = __ldg(cpt + (size_t)nfull * N_TOTAL);  // only first `rem` entries valid
        {
            float4 a = __ldg(yv + (size_t)c.x * 2), b = __ldg(yv + (size_t)c.x * 2 + 1);
            lo.x += a.x; lo.y += a.y; lo.z += a.z; lo.w += a.w;
            hi.x += b.x; hi.y += b.y; hi.z += b.z; hi.w += b.w;
        }
        if (rem > 1) {
            float4 a = __ldg(yv + (size_t)c.y * 2), b = __ldg(yv + (size_t)c.y * 2 + 1);
            lo.x += a.x; lo.y += a.y; lo.z += a.z; lo.w += a.w;
            hi.x += b.x; hi.y += b.y; hi.z += b.z; hi.w += b.w;
        }
        if (rem > 2) {
            float4 a = __ldg(yv + (size_t)c.z * 2), b = __ldg(yv + (size_t)c.z * 2 + 1);
            lo.x += a.x; lo.y += a.y; lo.z += a.z; lo.w += a.w;
            hi.x += b.x; hi.y += b.y; hi.z += b.z; hi.w += b.w;
        }
    }
}

// ---------------- fused gather + MLP (+ next-layer wa), 1 lane/node ----------------
// flip=0: read g_ya, write g_yb ; flip=1: read g_yb, write g_ya
__global__ void __launch_bounds__(256) k_gather_mlp(int flip,
                             const float* __restrict__ ba, const float* __restrict__ wb,
                             const float* __restrict__ bb, const float* __restrict__ wan) {
    const float* yin  = flip ? g_yb : g_ya;
    float*       yout = flip ? g_ya : g_yb;

    __shared__ float swb[64], swan[64], sba[8], sbb[8];
    int t = threadIdx.x;
    if (t < 64) { swb[t] = wb[t]; swan[t] = wan[t]; }
    if (t < 8)  { sba[t] = ba[t]; sbb[t] = bb[t]; }
    __syncthreads();

    unsigned node = blockIdx.x * blockDim.x + t;
    if (node >= (unsigned)N_TOTAL) return;

    float4 lo, hi;
    gather_node(yin, node, lo, hi);
    float in[8] = {lo.x, lo.y, lo.z, lo.w, hi.x, hi.y, hi.z, hi.w};

    float t1[8];
#pragma unroll
    for (int j = 0; j < 8; j++) t1[j] = leaky(in[j] + sba[j]);
    float t2[8];
#pragma unroll
    for (int j = 0; j < 8; j++) t2[j] = sbb[j];
#pragma unroll
    for (int k = 0; k < 8; k++) {
        float v = t1[k];
#pragma unroll
        for (int j = 0; j < 8; j++) t2[j] = fmaf(v, swb[k * 8 + j], t2[j]);
    }
#pragma unroll
    for (int j = 0; j < 8; j++) t2[j] = leaky(t2[j]);   // inter-layer act

    // next-layer pre-transform (wa of next layer folded by linearity)
    float y[8];
#pragma unroll
    for (int j = 0; j < 8; j++) y[j] = 0.f;
#pragma unroll
    for (int k = 0; k < 8; k++) {
        float v = t2[k];
#pragma unroll
        for (int j = 0; j < 8; j++) y[j] = fmaf(v, swan[k * 8 + j], y[j]);
    }
    float4* py = reinterpret_cast<float4*>(yout + (size_t)node * 8);
    py[0] = make_float4(y[0], y[1], y[2], y[3]);
    py[1] = make_float4(y[4], y[5], y[6], y[7]);
}

// Last layer (reads g_yb): z = fc1( leaky( leaky(agg + b3a) @ w3b + b3b ) )
__global__ void __launch_bounds__(256) k_gather_last(
                              const float* __restrict__ ba, const float* __restrict__ wb,
                              const float* __restrict__ bb,
                              const float* __restrict__ fc1w, const float* __restrict__ fc1b) {
    const float* yin = g_yb;

    __shared__ float swb[64], sba[8], sbb[8], sf1[8], sf1b;
    int t = threadIdx.x;
    if (t < 64) swb[t] = wb[t];
    if (t < 8)  { sba[t] = ba[t]; sbb[t] = bb[t]; sf1[t] = fc1w[t]; }
    if (t == 0) sf1b = fc1b[0];
    __syncthreads();

    unsigned node = blockIdx.x * blockDim.x + t;
    if (node >= (unsigned)N_TOTAL) return;

    float4 lo, hi;
    gather_node(yin, node, lo, hi);
    float in[8] = {lo.x, lo.y, lo.z, lo.w, hi.x, hi.y, hi.z, hi.w};

    float t1[8];
#pragma unroll
    for (int j = 0; j < 8; j++) t1[j] = leaky(in[j] + sba[j]);
    float t2[8];
#pragma unroll
    for (int j = 0; j < 8; j++) t2[j] = sbb[j];
#pragma unroll
    for (int k = 0; k < 8; k++) {
        float v = t1[k];
#pragma unroll
        for (int j = 0; j < 8; j++) t2[j] = fmaf(v, swb[k * 8 + j], t2[j]);
    }
    // no inter-layer act; readout applies leaky before fc1
    float z = sf1b;
#pragma unroll
    for (int j = 0; j < 8; j++) z = fmaf(leaky(t2[j]), sf1[j], z);
    g_z[node] = z;
}

// ---------------- readout: per-graph fc2 + log_softmax ----------------
__global__ void readout_kernel(const float* __restrict__ fc2w, const float* __restrict__ fc2b,
                               float* __restrict__ out) {
    int b = blockIdx.x;
    int t = threadIdx.x;
    float s0 = 0.f, s1 = 0.f;
    const float* zb = g_z + (size_t)b * N_NODES;
    for (int n = t; n < N_NODES; n += blockDim.x) {
        float zv = leaky(zb[n]);
        float2 w = __ldg(reinterpret_cast<const float2*>(fc2w) + n);
        s0 = fmaf(zv, w.x, s0);
        s1 = fmaf(zv, w.y, s1);
    }
#pragma unroll
    for (int o = 16; o > 0; o >>= 1) {
        s0 += __shfl_down_sync(0xFFFFFFFFu, s0, o);
        s1 += __shfl_down_sync(0xFFFFFFFFu, s1, o);
    }
    __shared__ float r0[8], r1[8];
    int w = t >> 5, lane = t & 31;
    if (lane == 0) { r0[w] = s0; r1[w] = s1; }
    __syncthreads();
    if (t == 0) {
        float a0 = 0.f, a1 = 0.f;
#pragma unroll
        for (int k = 0; k < 8; k++) { a0 += r0[k]; a1 += r1[k]; }
        a0 += fc2b[0];
        a1 += fc2b[1];
        float mx = fmaxf(a0, a1);
        float lse = mx + logf(expf(a0 - mx) + expf(a1 - mx));
        out[2 * b + 0] = a0 - lse;
        out[2 * b + 1] = a1 - lse;
    }
}

extern "C" void kernel_launch(void* const* d_in, const int* in_sizes, int n_in,
                              void* d_out, int out_size) {
    const float* x  = (const float*)d_in[0];
    const int*   ei = (const int*)d_in[1];

    int base = (in_sizes[2] == 128) ? 2 : 3;   // batch_size may not be materialized

    const float* W[16];
    for (int k = 0; k < 16; k++) W[k] = (const float*)d_in[base + k];
    const float* fc1w = (const float*)d_in[base + 16];
    const float* fc1b = (const float*)d_in[base + 17];
    const float* fc2w = (const float*)d_in[base + 18];
    const float* fc2b = (const float*)d_in[base + 19];
    float* out = (float*)d_out;

    const int TB = 256;
    unsigned pairEdgeBlocks = ((N_EDGES / 2) + TB - 1) / TB;
    unsigned nodeBlocks = (N_TOTAL + TB - 1) / TB;

    // pre also zeroes cursors; fill must follow it
    k_pre<<<nodeBlocks, TB>>>(x, W[0]);                                   // g_ya = x @ w0a, cursor = 0
    k_fill<<<pairEdgeBlocks, TB>>>(ei);

    k_gather_mlp<<<nodeBlocks, TB>>>(0, W[1], W[2], W[3], W[4]);          // L0: ya -> yb (w1a folded)
    k_gather_mlp<<<nodeBlocks, TB>>>(1, W[5], W[6], W[7], W[8]);          // L1: yb -> ya
    k_gather_mlp<<<nodeBlocks, TB>>>(0, W[9], W[10], W[11], W[12]);       // L2: ya -> yb
    k_gather_last<<<nodeBlocks, TB>>>(W[13], W[14], W[15], fc1w, fc1b);   // L3 + fc1 -> g_z

    readout_kernel<<<BATCH, TB>>>(fc2w, fc2b, out);
}

// round 12
// speedup vs baseline: 1.2156x; 1.2156x over previous
#include <cuda_runtime.h>

#define N_NODES 2000
#define BATCH 512
#define N_TOTAL (BATCH * N_NODES)      // 1,024,000
#define N_EDGES (16 * N_TOTAL)         // 16,384,000
#define SLOPE 0.01f
#define SLOTS 64                       // max degree; Poisson(16) tail @64 over 1M nodes ~ 1e-21
#define PLANES (SLOTS / 4)             // 16 planes of int4 (4 slots each)

// -------- device scratch (no allocation; BSS zero-init) --------
// Device globals are referenced ONLY from device code.
__device__ __align__(16) int  g_cursor[N_TOTAL];                    // degree after fill
__device__ __align__(16) int4 g_colT[(size_t)PLANES * N_TOTAL];     // transposed slot planes (hot: low planes)
__device__ __align__(16) float g_ya[(size_t)N_TOTAL * 8];
__device__ __align__(16) float g_yb[(size_t)N_TOTAL * 8];
__device__ __align__(16) float g_z[N_TOTAL];

__device__ __forceinline__ float leaky(float v) { return v > 0.0f ? v : SLOPE * v; }

// ---------------- pretransform + cursor zeroing ----------------
__global__ void k_pre(const float* __restrict__ x, const float* __restrict__ w0a) {
    __shared__ float sw[128];
    int t = threadIdx.x;
    if (t < 128) sw[t] = w0a[t];
    __syncthreads();
    unsigned i = blockIdx.x * blockDim.x + t;
    if (i >= (unsigned)N_TOTAL) return;

    g_cursor[i] = 0;   // coalesced; replaces a separate zero kernel

    float in[16];
    const float4* ax = reinterpret_cast<const float4*>(x + (size_t)i * 16);
#pragma unroll
    for (int q = 0; q < 4; q++) {
        float4 a = ax[q];
        in[4 * q] = a.x; in[4 * q + 1] = a.y; in[4 * q + 2] = a.z; in[4 * q + 3] = a.w;
    }
    float y[8];
#pragma unroll
    for (int j = 0; j < 8; j++) y[j] = 0.f;
#pragma unroll
    for (int k = 0; k < 16; k++) {
        float v = in[k];
#pragma unroll
        for (int j = 0; j < 8; j++) y[j] = fmaf(v, sw[k * 8 + j], y[j]);
    }
    float4* py = reinterpret_cast<float4*>(g_ya + (size_t)i * 8);
    py[0] = make_float4(y[0], y[1], y[2], y[3]);
    py[1] = make_float4(y[4], y[5], y[6], y[7]);
}

// ---------------- fill: 2 edges per thread, transposed slot store ----------------
__global__ void k_fill(const int* __restrict__ ei) {
    unsigned p = blockIdx.x * blockDim.x + threadIdx.x;   // edge-pair index
    if (p < (unsigned)(N_EDGES / 2)) {
        int2 src = __ldg(reinterpret_cast<const int2*>(ei) + p);
        int2 dst = __ldg(reinterpret_cast<const int2*>(ei + N_EDGES) + p);
        int pos0 = atomicAdd(&g_cursor[dst.x], 1);
        if (pos0 < SLOTS)
            reinterpret_cast<int*>(g_colT)[((size_t)(pos0 >> 2) * N_TOTAL + dst.x) * 4 + (pos0 & 3)] = src.x;
        int pos1 = atomicAdd(&g_cursor[dst.y], 1);
        if (pos1 < SLOTS)
            reinterpret_cast<int*>(g_colT)[((size_t)(pos1 >> 2) * N_TOTAL + dst.y) * 4 + (pos1 & 3)] = src.y;
    }
}

// ---------------- 2-lane gather helper (round-7 pattern: 1 wavefront/edge) ----------------
__device__ __forceinline__ float4 gather_half(const float* __restrict__ yin,
                                              unsigned node, unsigned half) {
    int deg = __ldg(&g_cursor[node]);
    if (deg > SLOTS) deg = SLOTS;

    float4 acc = *reinterpret_cast<const float4*>(yin + (size_t)node * 8 + half * 4);  // self
    int nfull = deg >> 2;
    const int4* cpt = g_colT + node;   // stride N_TOTAL between planes
    for (int p = 0; p < nfull; p++) {
        int4 c = __ldg(cpt + (size_t)p * N_TOTAL);
        float4 v0 = __ldg(reinterpret_cast<const float4*>(yin + (size_t)c.x * 8 + half * 4));
        float4 v1 = __ldg(reinterpret_cast<const float4*>(yin + (size_t)c.y * 8 + half * 4));
        float4 v2 = __ldg(reinterpret_cast<const float4*>(yin + (size_t)c.z * 8 + half * 4));
        float4 v3 = __ldg(reinterpret_cast<const float4*>(yin + (size_t)c.w * 8 + half * 4));
        acc.x += v0.x + v1.x + v2.x + v3.x;
        acc.y += v0.y + v1.y + v2.y + v3.y;
        acc.z += v0.z + v1.z + v2.z + v3.z;
        acc.w += v0.w + v1.w + v2.w + v3.w;
    }
    int rem = deg & 3;
    if (rem) {
        int4 c = __ldg(cpt + (size_t)nfull * N_TOTAL);   // only first `rem` valid
        {
            float4 v = __ldg(reinterpret_cast<const float4*>(yin + (size_t)c.x * 8 + half * 4));
            acc.x += v.x; acc.y += v.y; acc.z += v.z; acc.w += v.w;
        }
        if (rem > 1) {
            float4 v = __ldg(reinterpret_cast<const float4*>(yin + (size_t)c.y * 8 + half * 4));
            acc.x += v.x; acc.y += v.y; acc.z += v.z; acc.w += v.w;
        }
        if (rem > 2) {
            float4 v = __ldg(reinterpret_cast<const float4*>(yin + (size_t)c.z * 8 + half * 4));
            acc.x += v.x; acc.y += v.y; acc.z += v.z; acc.w += v.w;
        }
    }
    return acc;
}

// ---------------- fused gather + split-MLP (+ next-layer wa), 2 lanes/node ----------------
// flip=0: read g_ya, write g_yb ; flip=1: read g_yb, write g_ya
__global__ void __launch_bounds__(256) k_gather_mlp(int flip,
                             const float* __restrict__ ba, const float* __restrict__ wb,
                             const float* __restrict__ bb, const float* __restrict__ wan) {
    const float* yin  = flip ? g_yb : g_ya;
    float*       yout = flip ? g_ya : g_yb;

    __shared__ float swb[64], swan[64], sba[8], sbb[8];
    int t = threadIdx.x;
    if (t < 64) { swb[t] = wb[t]; swan[t] = wan[t]; }
    if (t < 8)  { sba[t] = ba[t]; sbb[t] = bb[t]; }
    __syncthreads();

    unsigned g = blockIdx.x * blockDim.x + t;   // 2 lanes per node
    unsigned node = g >> 1;
    unsigned half = g & 1u;
    int jo = half * 4;

    float4 acc = gather_half(yin, node, half);

    // exchange agg halves -> full in[8]
    float e0 = __shfl_xor_sync(0xFFFFFFFFu, acc.x, 1);
    float e1 = __shfl_xor_sync(0xFFFFFFFFu, acc.y, 1);
    float e2 = __shfl_xor_sync(0xFFFFFFFFu, acc.z, 1);
    float e3 = __shfl_xor_sync(0xFFFFFFFFu, acc.w, 1);
    float in[8];
    if (half == 0) {
        in[0] = acc.x; in[1] = acc.y; in[2] = acc.z; in[3] = acc.w;
        in[4] = e0; in[5] = e1; in[6] = e2; in[7] = e3;
    } else {
        in[0] = e0; in[1] = e1; in[2] = e2; in[3] = e3;
        in[4] = acc.x; in[5] = acc.y; in[6] = acc.z; in[7] = acc.w;
    }

    float t1[8];
#pragma unroll
    for (int j = 0; j < 8; j++) t1[j] = leaky(in[j] + sba[j]);

    // wb matvec: this lane computes ONLY its 4 output columns (halved duplication)
    float c0 = sbb[jo + 0], c1 = sbb[jo + 1], c2 = sbb[jo + 2], c3 = sbb[jo + 3];
#pragma unroll
    for (int k = 0; k < 8; k++) {
        float v = t1[k];
        c0 = fmaf(v, swb[k * 8 + jo + 0], c0);
        c1 = fmaf(v, swb[k * 8 + jo + 1], c1);
        c2 = fmaf(v, swb[k * 8 + jo + 2], c2);
        c3 = fmaf(v, swb[k * 8 + jo + 3], c3);
    }
    c0 = leaky(c0); c1 = leaky(c1); c2 = leaky(c2); c3 = leaky(c3);  // inter-layer act

    // exchange t2 halves -> full t2[8]
    float p0 = __shfl_xor_sync(0xFFFFFFFFu, c0, 1);
    float p1 = __shfl_xor_sync(0xFFFFFFFFu, c1, 1);
    float p2 = __shfl_xor_sync(0xFFFFFFFFu, c2, 1);
    float p3 = __shfl_xor_sync(0xFFFFFFFFu, c3, 1);
    float t2[8];
    if (half == 0) {
        t2[0] = c0; t2[1] = c1; t2[2] = c2; t2[3] = c3;
        t2[4] = p0; t2[5] = p1; t2[6] = p2; t2[7] = p3;
    } else {
        t2[0] = p0; t2[1] = p1; t2[2] = p2; t2[3] = p3;
        t2[4] = c0; t2[5] = c1; t2[6] = c2; t2[7] = c3;
    }

    // next-layer pre-transform: this lane's 4 output columns
    float y0 = 0.f, y1 = 0.f, y2 = 0.f, y3 = 0.f;
#pragma unroll
    for (int k = 0; k < 8; k++) {
        float v = t2[k];
        y0 = fmaf(v, swan[k * 8 + jo + 0], y0);
        y1 = fmaf(v, swan[k * 8 + jo + 1], y1);
        y2 = fmaf(v, swan[k * 8 + jo + 2], y2);
        y3 = fmaf(v, swan[k * 8 + jo + 3], y3);
    }
    *reinterpret_cast<float4*>(yout + (size_t)node * 8 + half * 4) = make_float4(y0, y1, y2, y3);
}

// Last layer (reads g_yb): z = fc1b + Σ leaky(t2)·fc1w, split across the lane pair
__global__ void __launch_bounds__(256) k_gather_last(
                              const float* __restrict__ ba, const float* __restrict__ wb,
                              const float* __restrict__ bb,
                              const float* __restrict__ fc1w, const float* __restrict__ fc1b) {
    const float* yin = g_yb;

    __shared__ float swb[64], sba[8], sbb[8], sf1[8], sf1b;
    int t = threadIdx.x;
    if (t < 64) swb[t] = wb[t];
    if (t < 8)  { sba[t] = ba[t]; sbb[t] = bb[t]; sf1[t] = fc1w[t]; }
    if (t == 0) sf1b = fc1b[0];
    __syncthreads();

    unsigned g = blockIdx.x * blockDim.x + t;
    unsigned node = g >> 1;
    unsigned half = g & 1u;
    int jo = half * 4;

    float4 acc = gather_half(yin, node, half);

    float e0 = __shfl_xor_sync(0xFFFFFFFFu, acc.x, 1);
    float e1 = __shfl_xor_sync(0xFFFFFFFFu, acc.y, 1);
    float e2 = __shfl_xor_sync(0xFFFFFFFFu, acc.z, 1);
    float e3 = __shfl_xor_sync(0xFFFFFFFFu, acc.w, 1);
    float in[8];
    if (half == 0) {
        in[0] = acc.x; in[1] = acc.y; in[2] = acc.z; in[3] = acc.w;
        in[4] = e0; in[5] = e1; in[6] = e2; in[7] = e3;
    } else {
        in[0] = e0; in[1] = e1; in[2] = e2; in[3] = e3;
        in[4] = acc.x; in[5] = acc.y; in[6] = acc.z; in[7] = acc.w;
    }

    float t1[8];
#pragma unroll
    for (int j = 0; j < 8; j++) t1[j] = leaky(in[j] + sba[j]);

    // own 4 columns of w3b (no inter-layer act on t2; fc1 applies leaky)
    float c0 = sbb[jo + 0], c1 = sbb[jo + 1], c2 = sbb[jo + 2], c3 = sbb[jo + 3];
#pragma unroll
    for (int k = 0; k < 8; k++) {
        float v = t1[k];
        c0 = fmaf(v, swb[k * 8 + jo + 0], c0);
        c1 = fmaf(v, swb[k * 8 + jo + 1], c1);
        c2 = fmaf(v, swb[k * 8 + jo + 2], c2);
        c3 = fmaf(v, swb[k * 8 + jo + 3], c3);
    }
    // partial fc1 dot over own 4 columns
    float zp = leaky(c0) * sf1[jo + 0] + leaky(c1) * sf1[jo + 1]
             + leaky(c2) * sf1[jo + 2] + leaky(c3) * sf1[jo + 3];
    zp += __shfl_xor_sync(0xFFFFFFFFu, zp, 1);
    if (half == 0) g_z[node] = zp + sf1b;
}

// ---------------- readout: per-graph fc2 + log_softmax ----------------
__global__ void readout_kernel(const float* __restrict__ fc2w, const float* __restrict__ fc2b,
                               float* __restrict__ out) {
    int b = blockIdx.x;
    int t = threadIdx.x;
    float s0 = 0.f, s1 = 0.f;
    const float* zb = g_z + (size_t)b * N_NODES;
    for (int n = t; n < N_NODES; n += blockDim.x) {
        float zv = leaky(zb[n]);
        float2 w = __ldg(reinterpret_cast<const float2*>(fc2w) + n);
        s0 = fmaf(zv, w.x, s0);
        s1 = fmaf(zv, w.y, s1);
    }
#pragma unroll
    for (int o = 16; o > 0; o >>= 1) {
        s0 += __shfl_down_sync(0xFFFFFFFFu, s0, o);
        s1 += __shfl_down_sync(0xFFFFFFFFu, s1, o);
    }
    __shared__ float r0[8], r1[8];
    int w = t >> 5, lane = t & 31;
    if (lane == 0) { r0[w] = s0; r1[w] = s1; }
    __syncthreads();
    if (t == 0) {
        float a0 = 0.f, a1 = 0.f;
#pragma unroll
        for (int k = 0; k < 8; k++) { a0 += r0[k]; a1 += r1[k]; }
        a0 += fc2b[0];
        a1 += fc2b[1];
        float mx = fmaxf(a0, a1);
        float lse = mx + logf(expf(a0 - mx) + expf(a1 - mx));
        out[2 * b + 0] = a0 - lse;
        out[2 * b + 1] = a1 - lse;
    }
}

extern "C" void kernel_launch(void* const* d_in, const int* in_sizes, int n_in,
                              void* d_out, int out_size) {
    const float* x  = (const float*)d_in[0];
    const int*   ei = (const int*)d_in[1];

    int base = (in_sizes[2] == 128) ? 2 : 3;   // batch_size may not be materialized

    const float* W[16];
    for (int k = 0; k < 16; k++) W[k] = (const float*)d_in[base + k];
    const float* fc1w = (const float*)d_in[base + 16];
    const float* fc1b = (const float*)d_in[base + 17];
    const float* fc2w = (const float*)d_in[base + 18];
    const float* fc2b = (const float*)d_in[base + 19];
    float* out = (float*)d_out;

    const int TB = 256;
    unsigned pairEdgeBlocks = ((N_EDGES / 2) + TB - 1) / TB;
    unsigned nodeBlocks = (N_TOTAL + TB - 1) / TB;
    unsigned pairBlocks = (N_TOTAL * 2) / TB;          // exact

    // pre also zeroes cursors; fill must follow it
    k_pre<<<nodeBlocks, TB>>>(x, W[0]);                                   // g_ya = x @ w0a, cursor = 0
    k_fill<<<pairEdgeBlocks, TB>>>(ei);

    k_gather_mlp<<<pairBlocks, TB>>>(0, W[1], W[2], W[3], W[4]);          // L0: ya -> yb (w1a folded)
    k_gather_mlp<<<pairBlocks, TB>>>(1, W[5], W[6], W[7], W[8]);          // L1: yb -> ya
    k_gather_mlp<<<pairBlocks, TB>>>(0, W[9], W[10], W[11], W[12]);       // L2: ya -> yb
    k_gather_last<<<pairBlocks, TB>>>(W[13], W[14], W[15], fc1w, fc1b);   // L3 + fc1 -> g_z

    readout_kernel<<<BATCH, TB>>>(fc2w, fc2b, out);
}